// round 1
// baseline (speedup 1.0000x reference)
#include <cuda_runtime.h>
#include <cuda_bf16.h>

// Problem constants (fixed by the dataset)
#define Bb     4
#define Kk     32
#define Ss     512
#define Hh     768
#define H3     2304   // 3*H
#define FINNER 3456   // int(3*H*1.5)
#define Mrows  4096   // B*K*K
#define NLEV   8      // doubling-table levels 1..8 (level 0 = token_reps)

// Scratch (device globals: allocation-free per harness rules)
__device__ float g_tab[NLEV][Bb][Ss][Hh];   // 50.3 MB  range-max doubling tables
__device__ float g_rel[Mrows][H3];          // 37.7 MB  concatenated [head|tail|context]
__device__ float g_hid[Mrows][FINNER];      // 56.6 MB  relu(rel@W1+b1)

__device__ __forceinline__ float4 fmax4(float4 a, float4 b) {
    return make_float4(fmaxf(a.x, b.x), fmaxf(a.y, b.y),
                       fmaxf(a.z, b.z), fmaxf(a.w, b.w));
}

// ---------------------------------------------------------------------------
// Sparse-table build: g_tab[lvl-1][b][s] = max(src[s], src[min(s+2^(lvl-1), S-1)])
// One block per (b,s) row, 192 threads x float4 covering H=768.
// ---------------------------------------------------------------------------
__global__ void build_level_kernel(const float* __restrict__ tok, int lvl) {
    int row  = blockIdx.x;          // 0 .. B*S-1
    int b    = row >> 9;
    int s    = row & (Ss - 1);
    int step = 1 << (lvl - 1);
    int s2   = min(s + step, Ss - 1);

    const float* src0 = (lvl == 1) ? tok + (size_t)row * Hh
                                   : &g_tab[lvl - 2][b][s][0];
    const float* src1 = (lvl == 1) ? tok + ((size_t)b * Ss + s2) * Hh
                                   : &g_tab[lvl - 2][b][s2][0];
    float* dst = &g_tab[lvl - 1][b][s][0];

    int t = threadIdx.x;            // 0..191 (float4 lanes)
    float4 a = ((const float4*)src0)[t];
    float4 c = ((const float4*)src1)[t];
    ((float4*)dst)[t] = fmax4(a, c);
}

// ---------------------------------------------------------------------------
// rel assembly: one block per (b,i,j) pair, 192 threads x float4.
// rel[row] = [ head(768) | tail(768) | context(768) ]
// context = range-max(token_reps[b, lo:hi]) if hi>lo else head  (bit-exact vs ref)
// ---------------------------------------------------------------------------
__global__ void build_rel_kernel(const float* __restrict__ csr,
                                 const int*   __restrict__ ids,
                                 const float* __restrict__ tok) {
    int pair = blockIdx.x;              // 0..4095
    int b  = pair >> 10;
    int ij = pair & 1023;
    int i  = ij >> 5;
    int j  = ij & 31;

    const int* pi = ids + (size_t)(b * Kk + i) * 2;
    const int* pj = ids + (size_t)(b * Kk + j) * 2;
    int si = pi[0], ei = pi[1];
    int sj = pj[0], ej = pj[1];
    int lo = min(ei, ej);               // min end
    int hi = max(si, sj);               // max start

    int t = threadIdx.x;                // 0..191
    float4 hv = ((const float4*)(csr + (size_t)(b * Kk + i) * Hh))[t];
    float4 tv = ((const float4*)(csr + (size_t)(b * Kk + j) * Hh))[t];
    float4 cv;

    if (hi > lo) {
        int len = hi - lo;              // >= 1
        int lvl = 31 - __clz(len);      // floor(log2(len)), 0..8
        int pw  = 1 << lvl;
        const float *r0, *r1;
        if (lvl == 0) {
            r0 = tok + ((size_t)b * Ss + lo) * Hh;
            r1 = tok + ((size_t)b * Ss + (hi - pw)) * Hh;
        } else {
            r0 = &g_tab[lvl - 1][b][lo][0];
            r1 = &g_tab[lvl - 1][b][hi - pw][0];
        }
        cv = fmax4(((const float4*)r0)[t], ((const float4*)r1)[t]);
    } else {
        cv = hv;                        // invalid range -> heads (matches jnp.where)
    }

    float* o = &g_rel[pair][0];
    ((float4*)(o))[t]          = hv;
    ((float4*)(o + Hh))[t]     = tv;
    ((float4*)(o + 2 * Hh))[t] = cv;
}

// ---------------------------------------------------------------------------
// fp32 SGEMM: C[M,N] = act(A[M,Kd] @ W[Kd,N] + bias[N]); act = relu if RELU.
// 128x128 block tile, BK=8, 8x8 per-thread micro-tile, 256 threads.
// All dims here are multiples of the tile sizes -> no bounds checks.
// ---------------------------------------------------------------------------
template <bool RELU>
__global__ __launch_bounds__(256, 2)
void sgemm_bias_kernel(const float* __restrict__ A,
                       const float* __restrict__ W,
                       const float* __restrict__ bias,
                       float*       __restrict__ C,
                       int M, int N, int Kd) {
    __shared__ __align__(16) float As[8][128];   // A tile, transposed (k-major)
    __shared__ __align__(16) float Bs[8][128];   // W tile

    const int tid = threadIdx.x;
    const int bm  = blockIdx.y << 7;
    const int bn  = blockIdx.x << 7;

    // A tile load: 128 rows x 8 k; 2 threads/row, float4 each
    const int a_row = tid >> 1;
    const int a_col = (tid & 1) << 2;
    // W tile load: 8 k-rows x 128 cols; 32 threads/row, float4 each
    const int b_row = tid >> 5;
    const int b_col = (tid & 31) << 2;

    const int tx = tid & 15;   // 16x16 thread grid
    const int ty = tid >> 4;

    float acc[8][8];
#pragma unroll
    for (int i = 0; i < 8; i++)
#pragma unroll
        for (int j = 0; j < 8; j++) acc[i][j] = 0.0f;

    const float* Ap = A + (size_t)(bm + a_row) * Kd + a_col;
    const float* Wp = W + (size_t)b_row * N + bn + b_col;

    for (int k0 = 0; k0 < Kd; k0 += 8) {
        float4 av = *(const float4*)(Ap + k0);
        As[a_col + 0][a_row] = av.x;
        As[a_col + 1][a_row] = av.y;
        As[a_col + 2][a_row] = av.z;
        As[a_col + 3][a_row] = av.w;
        *(float4*)&Bs[b_row][b_col] = *(const float4*)(Wp + (size_t)k0 * N);
        __syncthreads();

#pragma unroll
        for (int kk = 0; kk < 8; kk++) {
            float4 a0 = *(const float4*)&As[kk][ty * 8];
            float4 a1 = *(const float4*)&As[kk][ty * 8 + 4];
            float4 w0 = *(const float4*)&Bs[kk][tx * 8];
            float4 w1 = *(const float4*)&Bs[kk][tx * 8 + 4];
            float ra[8] = {a0.x, a0.y, a0.z, a0.w, a1.x, a1.y, a1.z, a1.w};
            float rb[8] = {w0.x, w0.y, w0.z, w0.w, w1.x, w1.y, w1.z, w1.w};
#pragma unroll
            for (int i = 0; i < 8; i++)
#pragma unroll
                for (int j = 0; j < 8; j++)
                    acc[i][j] = fmaf(ra[i], rb[j], acc[i][j]);
        }
        __syncthreads();
    }

    // Epilogue: bias (+ relu), vectorized stores
#pragma unroll
    for (int i = 0; i < 8; i++) {
        size_t row = (size_t)(bm + ty * 8 + i);
        float* crow = C + row * N + bn + tx * 8;
#pragma unroll
        for (int jj = 0; jj < 2; jj++) {
            int col = bn + tx * 8 + jj * 4;
            float4 v;
            v.x = acc[i][jj * 4 + 0] + __ldg(&bias[col + 0]);
            v.y = acc[i][jj * 4 + 1] + __ldg(&bias[col + 1]);
            v.z = acc[i][jj * 4 + 2] + __ldg(&bias[col + 2]);
            v.w = acc[i][jj * 4 + 3] + __ldg(&bias[col + 3]);
            if (RELU) {
                v.x = fmaxf(v.x, 0.0f);
                v.y = fmaxf(v.y, 0.0f);
                v.z = fmaxf(v.z, 0.0f);
                v.w = fmaxf(v.w, 0.0f);
            }
            *(float4*)(crow + jj * 4) = v;
        }
    }
}

// ---------------------------------------------------------------------------
// Launch: tables (8 levels) -> rel assembly -> GEMM1(relu) -> GEMM2
// ---------------------------------------------------------------------------
extern "C" void kernel_launch(void* const* d_in, const int* in_sizes, int n_in,
                              void* d_out, int out_size) {
    const float* csr = (const float*)d_in[0];   // cand_span_reps (B,K,H)
    const int*   ids = (const int*)  d_in[1];   // cand_span_ids  (B,K,2)
    const float* tok = (const float*)d_in[2];   // token_reps     (B,S,H)
    // d_in[3] token_masks: all-true, unused by the reference math
    const float* W1  = (const float*)d_in[4];   // (3H, INNER)
    const float* b1  = (const float*)d_in[5];   // (INNER,)
    const float* W2  = (const float*)d_in[6];   // (INNER, H)
    const float* b2  = (const float*)d_in[7];   // (H,)
    float*       out = (float*)d_out;           // (B, K*K, H)

    void *relp = nullptr, *hidp = nullptr;
    cudaGetSymbolAddress(&relp, g_rel);
    cudaGetSymbolAddress(&hidp, g_hid);

    for (int lvl = 1; lvl <= NLEV; lvl++)
        build_level_kernel<<<Bb * Ss, Hh / 4>>>(tok, lvl);

    build_rel_kernel<<<Mrows, Hh / 4>>>(csr, ids, tok);

    sgemm_bias_kernel<true><<<dim3(FINNER / 128, Mrows / 128), 256>>>(
        (const float*)relp, W1, b1, (float*)hidp, Mrows, FINNER, H3);

    sgemm_bias_kernel<false><<<dim3(Hh / 128, Mrows / 128), 256>>>(
        (const float*)hidp, W2, b2, out, Mrows, Hh, FINNER);
}

// round 3
// speedup vs baseline: 3.0211x; 3.0211x over previous
#include <cuda_runtime.h>
#include <cuda_bf16.h>
#include <cstdint>
#include <cstddef>

// Problem constants
#define Bb     4
#define Kk     32
#define Ss     512
#define Hh     768
#define H3     2304
#define FINNER 3456
#define Mrows  4096
#define NLEV   8

// ---------------- device scratch (allocation-free) ----------------
__device__ float         g_tab[NLEV][Bb][Ss][Hh];     // 50.3 MB range-max tables
__device__ __nv_bfloat16 gA1hi[Mrows][H3];            // rel, bf16 hi
__device__ __nv_bfloat16 gA1lo[Mrows][H3];            // rel, bf16 lo
__device__ __nv_bfloat16 gW1hi[FINNER][H3];           // W1^T hi  [n][k]
__device__ __nv_bfloat16 gW1lo[FINNER][H3];
__device__ __nv_bfloat16 gHhi[Mrows][FINNER];         // hidden hi
__device__ __nv_bfloat16 gHlo[Mrows][FINNER];
__device__ __nv_bfloat16 gW2hi[Hh][FINNER];           // W2^T hi  [n][k]
__device__ __nv_bfloat16 gW2lo[Hh][FINNER];

// ---------------- helpers ----------------
__device__ __forceinline__ uint32_t smem_to_u32(const void* p) {
    uint32_t a;
    asm("{ .reg .u64 t; cvta.to.shared.u64 t, %1; cvt.u32.u64 %0, t; }" : "=r"(a) : "l"(p));
    return a;
}

#define SMEM_SWIZZLE_128B(o) ((o) ^ (((o) >> 3) & 0x70))

__device__ __forceinline__ void cp16(uint32_t dst, const void* src) {
    asm volatile("cp.async.cg.shared.global [%0], [%1], 16;" :: "r"(dst), "l"(src));
}
#define CP_COMMIT()  asm volatile("cp.async.commit_group;" ::: "memory")
#define CP_WAIT2()   asm volatile("cp.async.wait_group 2;" ::: "memory")

__device__ __forceinline__ void ldsm_x4(uint32_t& r0, uint32_t& r1, uint32_t& r2, uint32_t& r3,
                                        uint32_t addr) {
    asm volatile("ldmatrix.sync.aligned.m8n8.x4.shared.b16 {%0,%1,%2,%3}, [%4];"
                 : "=r"(r0), "=r"(r1), "=r"(r2), "=r"(r3) : "r"(addr));
}

__device__ __forceinline__ void mma16816(float* c, const uint32_t* a, const uint32_t* b) {
    asm volatile(
        "mma.sync.aligned.m16n8k16.row.col.f32.bf16.bf16.f32 "
        "{%0,%1,%2,%3},{%4,%5,%6,%7},{%8,%9},{%0,%1,%2,%3};"
        : "+f"(c[0]), "+f"(c[1]), "+f"(c[2]), "+f"(c[3])
        : "r"(a[0]), "r"(a[1]), "r"(a[2]), "r"(a[3]), "r"(b[0]), "r"(b[1]));
}

__device__ __forceinline__ float4 fmax4(float4 a, float4 b) {
    return make_float4(fmaxf(a.x, b.x), fmaxf(a.y, b.y), fmaxf(a.z, b.z), fmaxf(a.w, b.w));
}

__device__ __forceinline__ void split_store4(__nv_bfloat16* ph, __nv_bfloat16* pl, float4 v) {
    __nv_bfloat16 h0 = __float2bfloat16(v.x), h1 = __float2bfloat16(v.y);
    __nv_bfloat16 h2 = __float2bfloat16(v.z), h3 = __float2bfloat16(v.w);
    __nv_bfloat16 l0 = __float2bfloat16(v.x - __bfloat162float(h0));
    __nv_bfloat16 l1 = __float2bfloat16(v.y - __bfloat162float(h1));
    __nv_bfloat16 l2 = __float2bfloat16(v.z - __bfloat162float(h2));
    __nv_bfloat16 l3 = __float2bfloat16(v.w - __bfloat162float(h3));
    *(ushort4*)ph = make_ushort4(__bfloat16_as_ushort(h0), __bfloat16_as_ushort(h1),
                                 __bfloat16_as_ushort(h2), __bfloat16_as_ushort(h3));
    *(ushort4*)pl = make_ushort4(__bfloat16_as_ushort(l0), __bfloat16_as_ushort(l1),
                                 __bfloat16_as_ushort(l2), __bfloat16_as_ushort(l3));
}

// ---------------------------------------------------------------------------
// Range-max doubling-table build (bit-exact vs reference)
// ---------------------------------------------------------------------------
__global__ void build_level_kernel(const float* __restrict__ tok, int lvl) {
    int row = blockIdx.x, b = row >> 9, s = row & (Ss - 1);
    int s2 = min(s + (1 << (lvl - 1)), Ss - 1);
    const float* src0 = (lvl == 1) ? tok + (size_t)row * Hh : &g_tab[lvl - 2][b][s][0];
    const float* src1 = (lvl == 1) ? tok + ((size_t)b * Ss + s2) * Hh : &g_tab[lvl - 2][b][s2][0];
    int t = threadIdx.x;
    ((float4*)&g_tab[lvl - 1][b][s][0])[t] =
        fmax4(((const float4*)src0)[t], ((const float4*)src1)[t]);
}

// ---------------------------------------------------------------------------
// rel assembly fused with bf16 hi/lo split
// ---------------------------------------------------------------------------
__global__ void convert_rel_kernel(const float* __restrict__ csr,
                                   const int*   __restrict__ ids,
                                   const float* __restrict__ tok) {
    int pair = blockIdx.x;
    int b = pair >> 10, ij = pair & 1023, i = ij >> 5, j = ij & 31;
    const int* pi = ids + (size_t)(b * Kk + i) * 2;
    const int* pj = ids + (size_t)(b * Kk + j) * 2;
    int lo = min(pi[1], pj[1]);
    int hi = max(pi[0], pj[0]);

    int t = threadIdx.x;
    float4 hv = ((const float4*)(csr + (size_t)(b * Kk + i) * Hh))[t];
    float4 tv = ((const float4*)(csr + (size_t)(b * Kk + j) * Hh))[t];
    float4 cv;
    if (hi > lo) {
        int len = hi - lo;
        int lvl = 31 - __clz(len);
        int pw  = 1 << lvl;
        const float *r0, *r1;
        if (lvl == 0) {
            r0 = tok + ((size_t)b * Ss + lo) * Hh;
            r1 = tok + ((size_t)b * Ss + (hi - pw)) * Hh;
        } else {
            r0 = &g_tab[lvl - 1][b][lo][0];
            r1 = &g_tab[lvl - 1][b][hi - pw][0];
        }
        cv = fmax4(((const float4*)r0)[t], ((const float4*)r1)[t]);
    } else {
        cv = hv;
    }
    split_store4(&gA1hi[pair][t * 4],        &gA1lo[pair][t * 4],        hv);
    split_store4(&gA1hi[pair][768 + t * 4],  &gA1lo[pair][768 + t * 4],  tv);
    split_store4(&gA1hi[pair][1536 + t * 4], &gA1lo[pair][1536 + t * 4], cv);
}

// ---------------------------------------------------------------------------
// Weight transpose + split: Wt[n][k] = W[k][n] -> bf16 hi/lo
// ---------------------------------------------------------------------------
__global__ void transpose_split_kernel(const float* __restrict__ W,
                                       __nv_bfloat16* __restrict__ Whi,
                                       __nv_bfloat16* __restrict__ Wlo,
                                       int Kd, int Nd) {
    __shared__ float tile[32][33];
    int k0 = blockIdx.x * 32, n0 = blockIdx.y * 32;
    int tx = threadIdx.x, ty = threadIdx.y;
#pragma unroll
    for (int r = ty; r < 32; r += 8)
        tile[r][tx] = W[(size_t)(k0 + r) * Nd + n0 + tx];
    __syncthreads();
#pragma unroll
    for (int r = ty; r < 32; r += 8) {
        float x = tile[tx][r];
        __nv_bfloat16 h = __float2bfloat16(x);
        size_t o = (size_t)(n0 + r) * Kd + k0 + tx;
        Whi[o] = h;
        Wlo[o] = __float2bfloat16(x - __bfloat162float(h));
    }
}

// ---------------------------------------------------------------------------
// mma.sync bf16 3-split GEMM: 128x128 CTA tile, BK=64, 3-stage cp.async.
// SMEM stage (64KB): Ahi | Alo | Bhi | Blo, each 128 rows x 128B, SW128.
// 8 warps: warp tile 64x32  (wm = wid>>2 in {0,1}, wn = wid&3 in {0..3}).
// ---------------------------------------------------------------------------
__device__ __forceinline__ void load_tile64(uint32_t sbuf, const __nv_bfloat16* g,
                                            int row0, int Kd, int k0, int tid) {
    const char* gp = (const char*)(g + (size_t)row0 * Kd + k0);
    size_t rs = (size_t)Kd * 2;
#pragma unroll
    for (int c = 0; c < 4; c++) {
        int idx = tid + c * 256;
        int row = idx >> 3, seg = idx & 7;
        uint32_t off = (uint32_t)(row * 128 + seg * 16);
        cp16(sbuf + SMEM_SWIZZLE_128B(off), gp + (size_t)row * rs + seg * 16);
    }
}

__device__ __forceinline__ void load_stage(uint32_t sbase,
    const __nv_bfloat16* Ahi, const __nv_bfloat16* Alo,
    const __nv_bfloat16* Bhi, const __nv_bfloat16* Blo,
    int bm, int bn, int Kd, int k0, int tid) {
    load_tile64(sbase,          Ahi, bm, Kd, k0, tid);
    load_tile64(sbase + 16384,  Alo, bm, Kd, k0, tid);
    load_tile64(sbase + 32768,  Bhi, bn, Kd, k0, tid);
    load_tile64(sbase + 49152,  Blo, bn, Kd, k0, tid);
}

#define STAGE_BYTES     65536u
#define GEMM_SMEM_BYTES (3 * 65536)

template <bool RELU, bool SPLIT_OUT>
__global__ __launch_bounds__(256, 1)
void gemm_mma_kernel(const __nv_bfloat16* __restrict__ Ahi,
                     const __nv_bfloat16* __restrict__ Alo,
                     const __nv_bfloat16* __restrict__ Bhi,
                     const __nv_bfloat16* __restrict__ Blo,
                     const float* __restrict__ bias,
                     __nv_bfloat16* __restrict__ Ohi,
                     __nv_bfloat16* __restrict__ Olo,
                     float* __restrict__ Of,
                     int N, int Kd) {
    extern __shared__ __align__(1024) char dsm[];
    const uint32_t tiles = smem_to_u32(dsm);

    const int tid = threadIdx.x, wid = tid >> 5, lane = tid & 31;
    const int bm = blockIdx.y << 7, bn = blockIdx.x << 7;
    const int wm = wid >> 2, wn = wid & 3;

    // ldmatrix per-lane geometry
    // A x4 (16x16): lanes 0-7 rows m..m+7 @k0 | 8-15 rows m+8.. @k0 | 16-23 rows m.. @+16B | 24-31 rows m+8.. @+16B
    const int arow = wm * 64 + (lane & 7) + 8 * ((lane >> 3) & 1);
    const int acol = ((lane >> 4) & 1) * 16;
    const uint32_t cxA = (uint32_t)(arow & 7) << 4;
    // B x4 (two n8 frags): lanes 0-7 rows n..n+7 @k0 | 8-15 same rows @+16B | 16-23 rows n+8.. @k0 | 24-31 rows n+8.. @+16B
    const int brow = wn * 32 + (lane & 7) + 8 * ((lane >> 4) & 1);
    const int bcol = ((lane >> 3) & 1) * 16;
    const uint32_t cxB = (uint32_t)(brow & 7) << 4;

    float acc[4][4][4];
#pragma unroll
    for (int mi = 0; mi < 4; mi++)
#pragma unroll
        for (int nj = 0; nj < 4; nj++)
#pragma unroll
            for (int q = 0; q < 4; q++) acc[mi][nj][q] = 0.0f;

    const int nIter = Kd >> 6;

    // prefetch 3 stages
#pragma unroll
    for (int s = 0; s < 3; s++) {
        load_stage(tiles + s * STAGE_BYTES, Ahi, Alo, Bhi, Blo, bm, bn, Kd, s * 64, tid);
        CP_COMMIT();
    }

    int buf = 0;
    for (int it = 0; it < nIter; ++it) {
        CP_WAIT2();              // stage `it` complete (empty groups keep count aligned)
        __syncthreads();

        const uint32_t sb  = tiles + (uint32_t)buf * STAGE_BYTES;
        const uint32_t sAh = sb,          sAl = sb + 16384u;
        const uint32_t sBh = sb + 32768u, sBl = sb + 49152u;

#pragma unroll
        for (int ks = 0; ks < 4; ks++) {
            const uint32_t aoff = (uint32_t)(arow * 128) + (((uint32_t)(ks * 32 + acol)) ^ cxA);
            const uint32_t boff = (uint32_t)(brow * 128) + (((uint32_t)(ks * 32 + bcol)) ^ cxB);

            uint32_t ah[4][4], al[4][4], bh[4][2], bl[4][2];
#pragma unroll
            for (int mi = 0; mi < 4; mi++) {
                ldsm_x4(ah[mi][0], ah[mi][1], ah[mi][2], ah[mi][3], sAh + aoff + mi * 2048u);
                ldsm_x4(al[mi][0], al[mi][1], al[mi][2], al[mi][3], sAl + aoff + mi * 2048u);
            }
#pragma unroll
            for (int p = 0; p < 2; p++) {
                ldsm_x4(bh[2 * p][0], bh[2 * p][1], bh[2 * p + 1][0], bh[2 * p + 1][1],
                        sBh + boff + p * 2048u);
                ldsm_x4(bl[2 * p][0], bl[2 * p][1], bl[2 * p + 1][0], bl[2 * p + 1][1],
                        sBl + boff + p * 2048u);
            }
#pragma unroll
            for (int mi = 0; mi < 4; mi++)
#pragma unroll
                for (int nj = 0; nj < 4; nj++) {
                    mma16816(acc[mi][nj], ah[mi], bh[nj]);
                    mma16816(acc[mi][nj], ah[mi], bl[nj]);
                    mma16816(acc[mi][nj], al[mi], bh[nj]);
                }
        }

        __syncthreads();         // all warps done reading buf before refill
        if (it + 3 < nIter)
            load_stage(sb, Ahi, Alo, Bhi, Blo, bm, bn, Kd, (it + 3) * 64, tid);
        CP_COMMIT();             // unconditional: keeps wait_group accounting exact
        buf = (buf == 2) ? 0 : buf + 1;
    }

    // epilogue
#pragma unroll
    for (int mi = 0; mi < 4; mi++) {
        const int r0 = bm + wm * 64 + mi * 16 + (lane >> 2);
#pragma unroll
        for (int nj = 0; nj < 4; nj++) {
            const int n = bn + wn * 32 + nj * 8 + 2 * (lane & 3);
            const float bz0 = __ldg(&bias[n]), bz1 = __ldg(&bias[n + 1]);
            float x0 = acc[mi][nj][0] + bz0, x1 = acc[mi][nj][1] + bz1;
            float x2 = acc[mi][nj][2] + bz0, x3 = acc[mi][nj][3] + bz1;
            if (RELU) {
                x0 = fmaxf(x0, 0.f); x1 = fmaxf(x1, 0.f);
                x2 = fmaxf(x2, 0.f); x3 = fmaxf(x3, 0.f);
            }
            if (SPLIT_OUT) {
                __nv_bfloat16 h0 = __float2bfloat16(x0), h1 = __float2bfloat16(x1);
                __nv_bfloat16 h2 = __float2bfloat16(x2), h3 = __float2bfloat16(x3);
                __nv_bfloat16 l0 = __float2bfloat16(x0 - __bfloat162float(h0));
                __nv_bfloat16 l1 = __float2bfloat16(x1 - __bfloat162float(h1));
                __nv_bfloat16 l2 = __float2bfloat16(x2 - __bfloat162float(h2));
                __nv_bfloat16 l3 = __float2bfloat16(x3 - __bfloat162float(h3));
                *(uint32_t*)(Ohi + (size_t)r0 * N + n) =
                    (uint32_t)__bfloat16_as_ushort(h0) | ((uint32_t)__bfloat16_as_ushort(h1) << 16);
                *(uint32_t*)(Olo + (size_t)r0 * N + n) =
                    (uint32_t)__bfloat16_as_ushort(l0) | ((uint32_t)__bfloat16_as_ushort(l1) << 16);
                *(uint32_t*)(Ohi + (size_t)(r0 + 8) * N + n) =
                    (uint32_t)__bfloat16_as_ushort(h2) | ((uint32_t)__bfloat16_as_ushort(h3) << 16);
                *(uint32_t*)(Olo + (size_t)(r0 + 8) * N + n) =
                    (uint32_t)__bfloat16_as_ushort(l2) | ((uint32_t)__bfloat16_as_ushort(l3) << 16);
            } else {
                *(float2*)(Of + (size_t)r0 * N + n)       = make_float2(x0, x1);
                *(float2*)(Of + (size_t)(r0 + 8) * N + n) = make_float2(x2, x3);
            }
        }
    }
}

// ---------------------------------------------------------------------------
// Launch graph
// ---------------------------------------------------------------------------
extern "C" void kernel_launch(void* const* d_in, const int* in_sizes, int n_in,
                              void* d_out, int out_size) {
    const float* csr = (const float*)d_in[0];
    const int*   ids = (const int*)  d_in[1];
    const float* tok = (const float*)d_in[2];
    const float* W1  = (const float*)d_in[4];
    const float* b1  = (const float*)d_in[5];
    const float* W2  = (const float*)d_in[6];
    const float* b2  = (const float*)d_in[7];
    float*       out = (float*)d_out;

    void *a1h, *a1l, *w1h, *w1l, *hh, *hl, *w2h, *w2l;
    cudaGetSymbolAddress(&a1h, gA1hi);  cudaGetSymbolAddress(&a1l, gA1lo);
    cudaGetSymbolAddress(&w1h, gW1hi);  cudaGetSymbolAddress(&w1l, gW1lo);
    cudaGetSymbolAddress(&hh,  gHhi);   cudaGetSymbolAddress(&hl,  gHlo);
    cudaGetSymbolAddress(&w2h, gW2hi);  cudaGetSymbolAddress(&w2l, gW2lo);

    cudaFuncSetAttribute(gemm_mma_kernel<true,  true>,
                         cudaFuncAttributeMaxDynamicSharedMemorySize, GEMM_SMEM_BYTES);
    cudaFuncSetAttribute(gemm_mma_kernel<false, false>,
                         cudaFuncAttributeMaxDynamicSharedMemorySize, GEMM_SMEM_BYTES);

    for (int lvl = 1; lvl <= NLEV; lvl++)
        build_level_kernel<<<Bb * Ss, Hh / 4>>>(tok, lvl);

    convert_rel_kernel<<<Mrows, Hh / 4>>>(csr, ids, tok);

    transpose_split_kernel<<<dim3(H3 / 32, FINNER / 32), dim3(32, 8)>>>(
        W1, (__nv_bfloat16*)w1h, (__nv_bfloat16*)w1l, H3, FINNER);
    transpose_split_kernel<<<dim3(FINNER / 32, Hh / 32), dim3(32, 8)>>>(
        W2, (__nv_bfloat16*)w2h, (__nv_bfloat16*)w2l, FINNER, Hh);

    gemm_mma_kernel<true, true><<<dim3(FINNER / 128, Mrows / 128), 256, GEMM_SMEM_BYTES>>>(
        (const __nv_bfloat16*)a1h, (const __nv_bfloat16*)a1l,
        (const __nv_bfloat16*)w1h, (const __nv_bfloat16*)w1l,
        b1, (__nv_bfloat16*)hh, (__nv_bfloat16*)hl, nullptr, FINNER, H3);

    gemm_mma_kernel<false, false><<<dim3(Hh / 128, Mrows / 128), 256, GEMM_SMEM_BYTES>>>(
        (const __nv_bfloat16*)hh, (const __nv_bfloat16*)hl,
        (const __nv_bfloat16*)w2h, (const __nv_bfloat16*)w2l,
        b2, nullptr, nullptr, out, Hh, FINNER);
}

// round 4
// speedup vs baseline: 5.5705x; 1.8439x over previous
#include <cuda_runtime.h>
#include <cuda_bf16.h>
#include <cstdint>
#include <cstddef>

// Problem constants
#define Bb     4
#define Kk     32
#define Ss     512
#define Hh     768
#define H3     2304
#define FINNER 3456
#define Mrows  4096
#define NLEV   8
#define NCAN   528            // canonical (i<=j) pairs per batch
#define NCANP  544            // padded per batch (17*128 total)
#define MCTX   2176           // 4 * 544

// ---------------- device scratch (allocation-free) ----------------
__device__ float         g_tab[NLEV][Bb][Ss][Hh];       // 50.3 MB
__device__ __nv_bfloat16 gCsrHi[Bb * Kk][Hh];           // csr hi
__device__ __nv_bfloat16 gCsrLo[Bb * Kk][Hh];
__device__ __nv_bfloat16 gCtxHi[MCTX][Hh];              // canonical contexts
__device__ __nv_bfloat16 gCtxLo[MCTX][Hh];
__device__ __nv_bfloat16 gW1hi[FINNER][H3];             // W1^T hi  [n][k]
__device__ __nv_bfloat16 gW1lo[FINNER][H3];
__device__ float         gPsl[3][Bb * Kk][FINNER];      // head*W1a | tail*W1b | head*W1c
__device__ float         gPc[MCTX][FINNER];             // ctx*W1c
__device__ __nv_bfloat16 gHhi[Mrows][FINNER];           // hidden hi
__device__ __nv_bfloat16 gHlo[Mrows][FINNER];
__device__ __nv_bfloat16 gW2hi[Hh][FINNER];             // W2^T hi  [n][k]
__device__ __nv_bfloat16 gW2lo[Hh][FINNER];

// ---------------- helpers ----------------
__device__ __forceinline__ uint32_t smem_to_u32(const void* p) {
    uint32_t a;
    asm("{ .reg .u64 t; cvta.to.shared.u64 t, %1; cvt.u32.u64 %0, t; }" : "=r"(a) : "l"(p));
    return a;
}

#define SMEM_SWIZZLE_128B(o) ((o) ^ (((o) >> 3) & 0x70))

__device__ __forceinline__ void cp16(uint32_t dst, const void* src) {
    asm volatile("cp.async.cg.shared.global [%0], [%1], 16;" :: "r"(dst), "l"(src));
}
#define CP_COMMIT()  asm volatile("cp.async.commit_group;" ::: "memory")
#define CP_WAIT2()   asm volatile("cp.async.wait_group 2;" ::: "memory")

__device__ __forceinline__ void ldsm_x4(uint32_t& r0, uint32_t& r1, uint32_t& r2, uint32_t& r3,
                                        uint32_t addr) {
    asm volatile("ldmatrix.sync.aligned.m8n8.x4.shared.b16 {%0,%1,%2,%3}, [%4];"
                 : "=r"(r0), "=r"(r1), "=r"(r2), "=r"(r3) : "r"(addr));
}

__device__ __forceinline__ void mma16816(float* c, const uint32_t* a, const uint32_t* b) {
    asm volatile(
        "mma.sync.aligned.m16n8k16.row.col.f32.bf16.bf16.f32 "
        "{%0,%1,%2,%3},{%4,%5,%6,%7},{%8,%9},{%0,%1,%2,%3};"
        : "+f"(c[0]), "+f"(c[1]), "+f"(c[2]), "+f"(c[3])
        : "r"(a[0]), "r"(a[1]), "r"(a[2]), "r"(a[3]), "r"(b[0]), "r"(b[1]));
}

__device__ __forceinline__ float4 fmax4(float4 a, float4 b) {
    return make_float4(fmaxf(a.x, b.x), fmaxf(a.y, b.y), fmaxf(a.z, b.z), fmaxf(a.w, b.w));
}

__device__ __forceinline__ void split_store4(__nv_bfloat16* ph, __nv_bfloat16* pl, float4 v) {
    __nv_bfloat16 h0 = __float2bfloat16(v.x), h1 = __float2bfloat16(v.y);
    __nv_bfloat16 h2 = __float2bfloat16(v.z), h3 = __float2bfloat16(v.w);
    __nv_bfloat16 l0 = __float2bfloat16(v.x - __bfloat162float(h0));
    __nv_bfloat16 l1 = __float2bfloat16(v.y - __bfloat162float(h1));
    __nv_bfloat16 l2 = __float2bfloat16(v.z - __bfloat162float(h2));
    __nv_bfloat16 l3 = __float2bfloat16(v.w - __bfloat162float(h3));
    *(ushort4*)ph = make_ushort4(__bfloat16_as_ushort(h0), __bfloat16_as_ushort(h1),
                                 __bfloat16_as_ushort(h2), __bfloat16_as_ushort(h3));
    *(ushort4*)pl = make_ushort4(__bfloat16_as_ushort(l0), __bfloat16_as_ushort(l1),
                                 __bfloat16_as_ushort(l2), __bfloat16_as_ushort(l3));
}

// ---------------------------------------------------------------------------
// Range-max doubling-table build (bit-exact vs reference)
// ---------------------------------------------------------------------------
__global__ void build_level_kernel(const float* __restrict__ tok, int lvl) {
    int row = blockIdx.x, b = row >> 9, s = row & (Ss - 1);
    int s2 = min(s + (1 << (lvl - 1)), Ss - 1);
    const float* src0 = (lvl == 1) ? tok + (size_t)row * Hh : &g_tab[lvl - 2][b][s][0];
    const float* src1 = (lvl == 1) ? tok + ((size_t)b * Ss + s2) * Hh : &g_tab[lvl - 2][b][s2][0];
    int t = threadIdx.x;
    ((float4*)&g_tab[lvl - 1][b][s][0])[t] =
        fmax4(((const float4*)src0)[t], ((const float4*)src1)[t]);
}

// ---------------------------------------------------------------------------
// csr -> bf16 hi/lo split (128 rows)
// ---------------------------------------------------------------------------
__global__ void split_csr_kernel(const float* __restrict__ csr) {
    int row = blockIdx.x, t = threadIdx.x;
    float4 v = ((const float4*)(csr + (size_t)row * Hh))[t];
    split_store4(&gCsrHi[row][t * 4], &gCsrLo[row][t * 4], v);
}

// ---------------------------------------------------------------------------
// Canonical context rows (i<=j, symmetric range-max), padded with zeros.
// ---------------------------------------------------------------------------
__global__ void build_ctx_kernel(const int* __restrict__ ids,
                                 const float* __restrict__ tok) {
    int r = blockIdx.x;                 // 0..2175
    int b = r / NCANP, t = r % NCANP;
    int tt = threadIdx.x;
    float4 cv = make_float4(0.f, 0.f, 0.f, 0.f);

    if (t < NCAN) {
        int i = 0, rem = t;
        while (rem >= 32 - i) { rem -= 32 - i; i++; }
        int j = i + rem;                // i <= j
        const int* pi = ids + (size_t)(b * Kk + i) * 2;
        const int* pj = ids + (size_t)(b * Kk + j) * 2;
        int lo = min(pi[1], pj[1]);
        int hi = max(pi[0], pj[0]);
        if (hi > lo) {
            int len = hi - lo;
            int lvl = 31 - __clz(len);
            int pw  = 1 << lvl;
            const float *r0, *r1;
            if (lvl == 0) {
                r0 = tok + ((size_t)b * Ss + lo) * Hh;
                r1 = tok + ((size_t)b * Ss + (hi - pw)) * Hh;
            } else {
                r0 = &g_tab[lvl - 1][b][lo][0];
                r1 = &g_tab[lvl - 1][b][hi - pw][0];
            }
            cv = fmax4(((const float4*)r0)[tt], ((const float4*)r1)[tt]);
        }
    }
    split_store4(&gCtxHi[r][tt * 4], &gCtxLo[r][tt * 4], cv);
}

// ---------------------------------------------------------------------------
// Weight transpose + split: Wt[n][k] = W[k][n] -> bf16 hi/lo
// ---------------------------------------------------------------------------
__global__ void transpose_split_kernel(const float* __restrict__ W,
                                       __nv_bfloat16* __restrict__ Whi,
                                       __nv_bfloat16* __restrict__ Wlo,
                                       int Kd, int Nd) {
    __shared__ float tile[32][33];
    int k0 = blockIdx.x * 32, n0 = blockIdx.y * 32;
    int tx = threadIdx.x, ty = threadIdx.y;
#pragma unroll
    for (int r = ty; r < 32; r += 8)
        tile[r][tx] = W[(size_t)(k0 + r) * Nd + n0 + tx];
    __syncthreads();
#pragma unroll
    for (int r = ty; r < 32; r += 8) {
        float x = tile[tx][r];
        __nv_bfloat16 h = __float2bfloat16(x);
        size_t o = (size_t)(n0 + r) * Kd + k0 + tx;
        Whi[o] = h;
        Wlo[o] = __float2bfloat16(x - __bfloat162float(h));
    }
}

// ---------------------------------------------------------------------------
// mma.sync bf16 3-split GEMM, fp32 output (+optional bias).
// CTA tile (MI*32) x 128, BK=64, 3-stage cp.async. 8 warps: wm in {0,1}
// covers MI*16 rows each; wn in {0..3} covers 32 cols each.
// ---------------------------------------------------------------------------
template <int AROWS>
__device__ __forceinline__ void load_tile(uint32_t sbuf, const __nv_bfloat16* g,
                                          int row0, int ld, int k0, int tid) {
    const char* gp = (const char*)(g + (size_t)row0 * ld + k0);
    size_t rs = (size_t)ld * 2;
#pragma unroll
    for (int c = 0; c < (AROWS * 8) / 256; c++) {
        int idx = tid + c * 256;
        int row = idx >> 3, seg = idx & 7;
        uint32_t off = (uint32_t)(row * 128 + seg * 16);
        cp16(sbuf + SMEM_SWIZZLE_128B(off), gp + (size_t)row * rs + seg * 16);
    }
}

template <int MI, bool HAS_BIAS>
__global__ __launch_bounds__(256, 1)
void gemm_mma_kernel(const __nv_bfloat16* __restrict__ Ahi,
                     const __nv_bfloat16* __restrict__ Alo,
                     const __nv_bfloat16* __restrict__ Bhi,
                     const __nv_bfloat16* __restrict__ Blo,
                     const float* __restrict__ bias,
                     float* __restrict__ Of,
                     int N, int Kd, int lda, int ldb,
                     int zB, long long zC) {
    constexpr uint32_t SA    = (uint32_t)MI * 4096u;       // A tile bytes (MI*32 rows x 128B)
    constexpr uint32_t STAGE = 2u * SA + 32768u;

    extern __shared__ __align__(1024) char dsm[];
    const uint32_t tiles = smem_to_u32(dsm);

    const int tid = threadIdx.x, wid = tid >> 5, lane = tid & 31;
    const int bm = blockIdx.y * (MI * 32);
    const int bn = blockIdx.x << 7;
    const int wm = wid >> 2, wn = wid & 3;

    Bhi += (size_t)blockIdx.z * zB;
    Blo += (size_t)blockIdx.z * zB;
    Of  += (size_t)blockIdx.z * zC;

    const int arow = wm * (MI * 16) + (lane & 7) + 8 * ((lane >> 3) & 1);
    const int acol = ((lane >> 4) & 1) * 16;
    const uint32_t cxA = (uint32_t)(arow & 7) << 4;
    const int brow = wn * 32 + (lane & 7) + 8 * ((lane >> 4) & 1);
    const int bcol = ((lane >> 3) & 1) * 16;
    const uint32_t cxB = (uint32_t)(brow & 7) << 4;

    float acc[MI][4][4];
#pragma unroll
    for (int mi = 0; mi < MI; mi++)
#pragma unroll
        for (int nj = 0; nj < 4; nj++)
#pragma unroll
            for (int q = 0; q < 4; q++) acc[mi][nj][q] = 0.0f;

    const int nIter = Kd >> 6;

    // prefetch 3 stages
#pragma unroll
    for (int s = 0; s < 3; s++) {
        uint32_t sb = tiles + s * STAGE;
        load_tile<MI * 32>(sb,               Ahi, bm, lda, s * 64, tid);
        load_tile<MI * 32>(sb + SA,          Alo, bm, lda, s * 64, tid);
        load_tile<128>    (sb + 2 * SA,      Bhi, bn, ldb, s * 64, tid);
        load_tile<128>    (sb + 2 * SA + 16384u, Blo, bn, ldb, s * 64, tid);
        CP_COMMIT();
    }

    int buf = 0;
    for (int it = 0; it < nIter; ++it) {
        CP_WAIT2();
        __syncthreads();

        const uint32_t sb  = tiles + (uint32_t)buf * STAGE;
        const uint32_t sAh = sb,              sAl = sb + SA;
        const uint32_t sBh = sb + 2 * SA,     sBl = sb + 2 * SA + 16384u;

#pragma unroll
        for (int ks = 0; ks < 4; ks++) {
            const uint32_t aoff = (uint32_t)(arow * 128) + (((uint32_t)(ks * 32 + acol)) ^ cxA);
            const uint32_t boff = (uint32_t)(brow * 128) + (((uint32_t)(ks * 32 + bcol)) ^ cxB);

            uint32_t ah[MI][4], al[MI][4], bh[4][2], bl[4][2];
#pragma unroll
            for (int mi = 0; mi < MI; mi++) {
                ldsm_x4(ah[mi][0], ah[mi][1], ah[mi][2], ah[mi][3], sAh + aoff + mi * 2048u);
                ldsm_x4(al[mi][0], al[mi][1], al[mi][2], al[mi][3], sAl + aoff + mi * 2048u);
            }
#pragma unroll
            for (int p = 0; p < 2; p++) {
                ldsm_x4(bh[2 * p][0], bh[2 * p][1], bh[2 * p + 1][0], bh[2 * p + 1][1],
                        sBh + boff + p * 2048u);
                ldsm_x4(bl[2 * p][0], bl[2 * p][1], bl[2 * p + 1][0], bl[2 * p + 1][1],
                        sBl + boff + p * 2048u);
            }
#pragma unroll
            for (int mi = 0; mi < MI; mi++)
#pragma unroll
                for (int nj = 0; nj < 4; nj++) {
                    mma16816(acc[mi][nj], ah[mi], bh[nj]);
                    mma16816(acc[mi][nj], ah[mi], bl[nj]);
                    mma16816(acc[mi][nj], al[mi], bh[nj]);
                }
        }

        __syncthreads();
        if (it + 3 < nIter) {
            load_tile<MI * 32>(sb,               Ahi, bm, lda, (it + 3) * 64, tid);
            load_tile<MI * 32>(sb + SA,          Alo, bm, lda, (it + 3) * 64, tid);
            load_tile<128>    (sb + 2 * SA,      Bhi, bn, ldb, (it + 3) * 64, tid);
            load_tile<128>    (sb + 2 * SA + 16384u, Blo, bn, ldb, (it + 3) * 64, tid);
        }
        CP_COMMIT();
        buf = (buf == 2) ? 0 : buf + 1;
    }

    // epilogue: fp32 (+bias)
#pragma unroll
    for (int mi = 0; mi < MI; mi++) {
        const int r0 = bm + wm * (MI * 16) + mi * 16 + (lane >> 2);
#pragma unroll
        for (int nj = 0; nj < 4; nj++) {
            const int n = bn + wn * 32 + nj * 8 + 2 * (lane & 3);
            float bz0 = 0.f, bz1 = 0.f;
            if (HAS_BIAS) { bz0 = __ldg(&bias[n]); bz1 = __ldg(&bias[n + 1]); }
            *(float2*)(Of + (size_t)r0 * N + n) =
                make_float2(acc[mi][nj][0] + bz0, acc[mi][nj][1] + bz1);
            *(float2*)(Of + (size_t)(r0 + 8) * N + n) =
                make_float2(acc[mi][nj][2] + bz0, acc[mi][nj][3] + bz1);
        }
    }
}

// ---------------------------------------------------------------------------
// Combine partials: hid = relu(Ph[b,i] + Pt[b,j] + (valid?Pc:Phc) + b1),
// split to bf16 hi/lo.
// ---------------------------------------------------------------------------
__global__ void combine_kernel(const int* __restrict__ ids,
                               const float* __restrict__ b1v) {
    int pair = blockIdx.x;
    int b = pair >> 10, i = (pair >> 5) & 31, j = pair & 31;
    const int* pi = ids + (size_t)(b * Kk + i) * 2;
    const int* pj = ids + (size_t)(b * Kk + j) * 2;
    int lo = min(pi[1], pj[1]);
    int hi = max(pi[0], pj[0]);
    bool valid = hi > lo;
    int ii = min(i, j), jj = max(i, j);
    int tri = 32 * ii - (ii * (ii - 1)) / 2 + (jj - ii);

    const float4* pa = (const float4*)&gPsl[0][b * Kk + i][0];
    const float4* pb = (const float4*)&gPsl[1][b * Kk + j][0];
    const float4* pc = valid ? (const float4*)&gPc[b * NCANP + tri][0]
                             : (const float4*)&gPsl[2][b * Kk + i][0];
    const float4* bb = (const float4*)b1v;

    for (int q = threadIdx.x; q < FINNER / 4; q += blockDim.x) {
        float4 va = pa[q], vb = pb[q], vc = pc[q], v1 = bb[q];
        float4 x = make_float4(fmaxf(va.x + vb.x + vc.x + v1.x, 0.f),
                               fmaxf(va.y + vb.y + vc.y + v1.y, 0.f),
                               fmaxf(va.z + vb.z + vc.z + v1.z, 0.f),
                               fmaxf(va.w + vb.w + vc.w + v1.w, 0.f));
        split_store4(&gHhi[pair][q * 4], &gHlo[pair][q * 4], x);
    }
}

// ---------------------------------------------------------------------------
// Launch graph
// ---------------------------------------------------------------------------
extern "C" void kernel_launch(void* const* d_in, const int* in_sizes, int n_in,
                              void* d_out, int out_size) {
    const float* csr = (const float*)d_in[0];
    const int*   ids = (const int*)  d_in[1];
    const float* tok = (const float*)d_in[2];
    const float* W1  = (const float*)d_in[4];
    const float* b1  = (const float*)d_in[5];
    const float* W2  = (const float*)d_in[6];
    const float* b2  = (const float*)d_in[7];
    float*       out = (float*)d_out;

    void *csrh, *csrl, *ctxh, *ctxl, *w1h, *w1l, *psl, *pc, *hh, *hl, *w2h, *w2l;
    cudaGetSymbolAddress(&csrh, gCsrHi);  cudaGetSymbolAddress(&csrl, gCsrLo);
    cudaGetSymbolAddress(&ctxh, gCtxHi);  cudaGetSymbolAddress(&ctxl, gCtxLo);
    cudaGetSymbolAddress(&w1h,  gW1hi);   cudaGetSymbolAddress(&w1l,  gW1lo);
    cudaGetSymbolAddress(&psl,  gPsl);    cudaGetSymbolAddress(&pc,   gPc);
    cudaGetSymbolAddress(&hh,   gHhi);    cudaGetSymbolAddress(&hl,   gHlo);
    cudaGetSymbolAddress(&w2h,  gW2hi);   cudaGetSymbolAddress(&w2l,  gW2lo);

    constexpr int SMEM_MI4 = 3 * (2 * 16384 + 32768);   // 192 KB
    constexpr int SMEM_MI2 = 3 * (2 * 8192 + 32768);    // 144 KB
    cudaFuncSetAttribute(gemm_mma_kernel<4, false>,
                         cudaFuncAttributeMaxDynamicSharedMemorySize, SMEM_MI4);
    cudaFuncSetAttribute(gemm_mma_kernel<2, true>,
                         cudaFuncAttributeMaxDynamicSharedMemorySize, SMEM_MI2);

    // 1) range-max tables
    for (int lvl = 1; lvl <= NLEV; lvl++)
        build_level_kernel<<<Bb * Ss, Hh / 4>>>(tok, lvl);

    // 2) operand prep
    split_csr_kernel<<<Bb * Kk, Hh / 4>>>(csr);
    build_ctx_kernel<<<MCTX, Hh / 4>>>(ids, tok);
    transpose_split_kernel<<<dim3(H3 / 32, FINNER / 32), dim3(32, 8)>>>(
        W1, (__nv_bfloat16*)w1h, (__nv_bfloat16*)w1l, H3, FINNER);
    transpose_split_kernel<<<dim3(FINNER / 32, Hh / 32), dim3(32, 8)>>>(
        W2, (__nv_bfloat16*)w2h, (__nv_bfloat16*)w2l, FINNER, Hh);

    // 3) Pslice: csr (128xH) x W1 slice z  -> gPsl[z]   (z in {head, tail, ctx-slice})
    gemm_mma_kernel<4, false><<<dim3(FINNER / 128, 1, 3), 256, SMEM_MI4>>>(
        (const __nv_bfloat16*)csrh, (const __nv_bfloat16*)csrl,
        (const __nv_bfloat16*)w1h,  (const __nv_bfloat16*)w1l,
        nullptr, (float*)psl,
        FINNER, Hh, Hh, H3, Hh, (long long)(Bb * Kk) * FINNER);

    // 4) ctx GEMM: canonical contexts x W1c -> gPc
    gemm_mma_kernel<4, false><<<dim3(FINNER / 128, MCTX / 128, 1), 256, SMEM_MI4>>>(
        (const __nv_bfloat16*)ctxh, (const __nv_bfloat16*)ctxl,
        (const __nv_bfloat16*)w1h + 2 * Hh, (const __nv_bfloat16*)w1l + 2 * Hh,
        nullptr, (float*)pc,
        FINNER, Hh, Hh, H3, 0, 0);

    // 5) combine partials -> hidden (relu, bf16 split)
    combine_kernel<<<Mrows, 256>>>(ids, b1);

    // 6) GEMM2: hidden x W2 + b2 -> out   (64x128 tiles: 384 CTAs, balanced)
    gemm_mma_kernel<2, true><<<dim3(Hh / 128, Mrows / 64, 1), 256, SMEM_MI2>>>(
        (const __nv_bfloat16*)hh, (const __nv_bfloat16*)hl,
        (const __nv_bfloat16*)w2h, (const __nv_bfloat16*)w2l,
        b2, out,
        Hh, FINNER, FINNER, FINNER, 0, 0);
}

// round 5
// speedup vs baseline: 7.9091x; 1.4198x over previous
#include <cuda_runtime.h>
#include <cuda_fp16.h>
#include <cstdint>
#include <cstddef>

// Problem constants
#define Bb     4
#define Kk     32
#define Ss     512
#define Hh     768
#define H3     2304
#define FINNER 3456
#define Mrows  4096
#define NCAN   528
#define NCANP  544
#define MCTX   2176

// ---------------- device scratch (allocation-free) ----------------
__device__ float  g_tab[4][Bb][Ss][Hh];           // 4-ary range-max tables (25 MB)
__device__ __half gCsrHi[Bb * Kk][Hh];
__device__ __half gCsrLo[Bb * Kk][Hh];
__device__ __half gCtxHi[MCTX][Hh];
__device__ __half gCtxLo[MCTX][Hh];
__device__ __half gW1h[FINNER][H3];               // W1^T fp16 [n][k]
__device__ float  gPsl[3][Bb * Kk][FINNER];       // head*W1a | tail*W1b | head*W1c
__device__ float  gPc[MCTX][FINNER];              // ctx*W1c
__device__ __half gHhi[Mrows][FINNER];
__device__ __half gHlo[Mrows][FINNER];
__device__ __half gW2h[Hh][FINNER];               // W2^T fp16 [n][k]

// ---------------- helpers ----------------
__device__ __forceinline__ uint32_t smem_to_u32(const void* p) {
    uint32_t a;
    asm("{ .reg .u64 t; cvta.to.shared.u64 t, %1; cvt.u32.u64 %0, t; }" : "=r"(a) : "l"(p));
    return a;
}

#define SMEM_SWIZZLE_128B(o) ((o) ^ (((o) >> 3) & 0x70))

__device__ __forceinline__ void cp16(uint32_t dst, const void* src) {
    asm volatile("cp.async.cg.shared.global [%0], [%1], 16;" :: "r"(dst), "l"(src));
}
#define CP_COMMIT()  asm volatile("cp.async.commit_group;" ::: "memory")
#define CP_WAIT2()   asm volatile("cp.async.wait_group 2;" ::: "memory")

__device__ __forceinline__ void ldsm_x4(uint32_t& r0, uint32_t& r1, uint32_t& r2, uint32_t& r3,
                                        uint32_t addr) {
    asm volatile("ldmatrix.sync.aligned.m8n8.x4.shared.b16 {%0,%1,%2,%3}, [%4];"
                 : "=r"(r0), "=r"(r1), "=r"(r2), "=r"(r3) : "r"(addr));
}

__device__ __forceinline__ void mma16816(float* c, const uint32_t* a, const uint32_t* b) {
    asm volatile(
        "mma.sync.aligned.m16n8k16.row.col.f32.f16.f16.f32 "
        "{%0,%1,%2,%3},{%4,%5,%6,%7},{%8,%9},{%0,%1,%2,%3};"
        : "+f"(c[0]), "+f"(c[1]), "+f"(c[2]), "+f"(c[3])
        : "r"(a[0]), "r"(a[1]), "r"(a[2]), "r"(a[3]), "r"(b[0]), "r"(b[1]));
}

__device__ __forceinline__ float4 fmax4(float4 a, float4 b) {
    return make_float4(fmaxf(a.x, b.x), fmaxf(a.y, b.y), fmaxf(a.z, b.z), fmaxf(a.w, b.w));
}

__device__ __forceinline__ void split_store4h(__half* ph, __half* pl, float4 v) {
    __half h0 = __float2half_rn(v.x), h1 = __float2half_rn(v.y);
    __half h2 = __float2half_rn(v.z), h3 = __float2half_rn(v.w);
    __half l0 = __float2half_rn(v.x - __half2float(h0));
    __half l1 = __float2half_rn(v.y - __half2float(h1));
    __half l2 = __float2half_rn(v.z - __half2float(h2));
    __half l3 = __float2half_rn(v.w - __half2float(h3));
    *(ushort4*)ph = make_ushort4(__half_as_ushort(h0), __half_as_ushort(h1),
                                 __half_as_ushort(h2), __half_as_ushort(h3));
    *(ushort4*)pl = make_ushort4(__half_as_ushort(l0), __half_as_ushort(l1),
                                 __half_as_ushort(l2), __half_as_ushort(l3));
}

// ---------------------------------------------------------------------------
// 4-ary range-max table: level m (block 4^m) from level m-1 (block 4^(m-1)).
// Max over 4 stepped entries; fp32 max is assoc/idempotent -> bit-exact covers.
// ---------------------------------------------------------------------------
__global__ void build_level4_kernel(const float* __restrict__ tok, int m) {
    int row = blockIdx.x, b = row >> 9, s = row & (Ss - 1);
    int q = 1 << (2 * (m - 1));
    int s1 = min(s + q, Ss - 1), s2 = min(s + 2 * q, Ss - 1), s3 = min(s + 3 * q, Ss - 1);
    const float *r0, *r1, *r2, *r3;
    if (m == 1) {
        const float* base = tok + (size_t)b * Ss * Hh;
        r0 = base + (size_t)s * Hh;  r1 = base + (size_t)s1 * Hh;
        r2 = base + (size_t)s2 * Hh; r3 = base + (size_t)s3 * Hh;
    } else {
        r0 = &g_tab[m - 2][b][s][0];  r1 = &g_tab[m - 2][b][s1][0];
        r2 = &g_tab[m - 2][b][s2][0]; r3 = &g_tab[m - 2][b][s3][0];
    }
    int t = threadIdx.x;
    ((float4*)&g_tab[m - 1][b][s][0])[t] =
        fmax4(fmax4(((const float4*)r0)[t], ((const float4*)r1)[t]),
              fmax4(((const float4*)r2)[t], ((const float4*)r3)[t]));
}

// ---------------------------------------------------------------------------
// csr -> fp16 hi/lo split
// ---------------------------------------------------------------------------
__global__ void split_csr_kernel(const float* __restrict__ csr) {
    int row = blockIdx.x, t = threadIdx.x;
    float4 v = ((const float4*)(csr + (size_t)row * Hh))[t];
    split_store4h(&gCsrHi[row][t * 4], &gCsrLo[row][t * 4], v);
}

// ---------------------------------------------------------------------------
// Canonical context rows (i<=j): range-max via <=4 overlapping 4^m blocks.
// ---------------------------------------------------------------------------
__global__ void build_ctx_kernel(const int* __restrict__ ids,
                                 const float* __restrict__ tok) {
    int r = blockIdx.x;
    int b = r / NCANP, t = r % NCANP;
    int tt = threadIdx.x;
    float4 cv = make_float4(0.f, 0.f, 0.f, 0.f);

    if (t < NCAN) {
        int i = 0, rem = t;
        while (rem >= 32 - i) { rem -= 32 - i; i++; }
        int j = i + rem;
        const int* pi = ids + (size_t)(b * Kk + i) * 2;
        const int* pj = ids + (size_t)(b * Kk + j) * 2;
        int lo = min(pi[1], pj[1]);
        int hi = max(pi[0], pj[0]);
        if (hi > lo) {
            int len = hi - lo;
            int m  = (31 - __clz(len)) >> 1;      // floor(log4 len)
            int p  = 1 << (2 * m);
            int d  = len - p;                      // 0 <= d <= 3p
            int s0 = lo;
            int s1 = lo + (d + 2) / 3;             // ceil(d/3)
            int s2 = lo + (2 * d + 2) / 3;         // ceil(2d/3)
            int s3 = hi - p;
            const float *q0, *q1, *q2, *q3;
            if (m == 0) {
                const float* base = tok + (size_t)b * Ss * Hh;
                q0 = base + (size_t)s0 * Hh; q1 = base + (size_t)s1 * Hh;
                q2 = base + (size_t)s2 * Hh; q3 = base + (size_t)s3 * Hh;
            } else {
                q0 = &g_tab[m - 1][b][s0][0]; q1 = &g_tab[m - 1][b][s1][0];
                q2 = &g_tab[m - 1][b][s2][0]; q3 = &g_tab[m - 1][b][s3][0];
            }
            cv = fmax4(fmax4(((const float4*)q0)[tt], ((const float4*)q1)[tt]),
                       fmax4(((const float4*)q2)[tt], ((const float4*)q3)[tt]));
        }
    }
    split_store4h(&gCtxHi[r][tt * 4], &gCtxLo[r][tt * 4], cv);
}

// ---------------------------------------------------------------------------
// Weight transpose to single fp16: Wt[n][k] = fp16(W[k][n])
// ---------------------------------------------------------------------------
__global__ void transpose_half_kernel(const float* __restrict__ W,
                                      __half* __restrict__ Wt,
                                      int Kd, int Nd) {
    __shared__ float tile[32][33];
    int k0 = blockIdx.x * 32, n0 = blockIdx.y * 32;
    int tx = threadIdx.x, ty = threadIdx.y;
#pragma unroll
    for (int r = ty; r < 32; r += 8)
        tile[r][tx] = W[(size_t)(k0 + r) * Nd + n0 + tx];
    __syncthreads();
#pragma unroll
    for (int r = ty; r < 32; r += 8)
        Wt[(size_t)(n0 + r) * Kd + k0 + tx] = __float2half_rn(tile[tx][r]);
}

// ---------------------------------------------------------------------------
// mma.sync fp16 2-product GEMM: C = (Ahi + Alo) * Bh  (+bias), fp32 out.
// CTA tile (MI*32) x 128, BK=64, 3-stage cp.async, 8 warps.
// ---------------------------------------------------------------------------
template <int AROWS>
__device__ __forceinline__ void load_tile(uint32_t sbuf, const __half* g,
                                          int row0, int ld, int k0, int tid) {
    const char* gp = (const char*)(g + (size_t)row0 * ld + k0);
    size_t rs = (size_t)ld * 2;
#pragma unroll
    for (int c = 0; c < (AROWS * 8) / 256; c++) {
        int idx = tid + c * 256;
        int row = idx >> 3, seg = idx & 7;
        uint32_t off = (uint32_t)(row * 128 + seg * 16);
        cp16(sbuf + SMEM_SWIZZLE_128B(off), gp + (size_t)row * rs + seg * 16);
    }
}

template <int MI, bool HAS_BIAS>
__global__ __launch_bounds__(256)
void gemm_mma_kernel(const __half* __restrict__ Ahi,
                     const __half* __restrict__ Alo,
                     const __half* __restrict__ Bh,
                     const float* __restrict__ bias,
                     float* __restrict__ Of,
                     int N, int Kd, int lda, int ldb,
                     int zB, long long zC) {
    constexpr uint32_t SA    = (uint32_t)MI * 4096u;
    constexpr uint32_t STAGE = 2u * SA + 16384u;

    extern __shared__ __align__(1024) char dsm[];
    const uint32_t tiles = smem_to_u32(dsm);

    const int tid = threadIdx.x, wid = tid >> 5, lane = tid & 31;
    const int bm = blockIdx.y * (MI * 32);
    const int bn = blockIdx.x << 7;
    const int wm = wid >> 2, wn = wid & 3;

    Bh += (size_t)blockIdx.z * zB;
    Of += (size_t)blockIdx.z * zC;

    const int arow = wm * (MI * 16) + (lane & 7) + 8 * ((lane >> 3) & 1);
    const int acol = ((lane >> 4) & 1) * 16;
    const uint32_t cxA = (uint32_t)(arow & 7) << 4;
    const int brow = wn * 32 + (lane & 7) + 8 * ((lane >> 4) & 1);
    const int bcol = ((lane >> 3) & 1) * 16;
    const uint32_t cxB = (uint32_t)(brow & 7) << 4;

    float acc[MI][4][4];
#pragma unroll
    for (int mi = 0; mi < MI; mi++)
#pragma unroll
        for (int nj = 0; nj < 4; nj++)
#pragma unroll
            for (int q = 0; q < 4; q++) acc[mi][nj][q] = 0.0f;

    const int nIter = Kd >> 6;

#pragma unroll
    for (int s = 0; s < 3; s++) {
        uint32_t sb = tiles + s * STAGE;
        load_tile<MI * 32>(sb,          Ahi, bm, lda, s * 64, tid);
        load_tile<MI * 32>(sb + SA,     Alo, bm, lda, s * 64, tid);
        load_tile<128>    (sb + 2 * SA, Bh,  bn, ldb, s * 64, tid);
        CP_COMMIT();
    }

    int buf = 0;
    for (int it = 0; it < nIter; ++it) {
        CP_WAIT2();
        __syncthreads();

        const uint32_t sb  = tiles + (uint32_t)buf * STAGE;
        const uint32_t sAh = sb, sAl = sb + SA, sBh = sb + 2 * SA;

#pragma unroll
        for (int ks = 0; ks < 4; ks++) {
            const uint32_t aoff = (uint32_t)(arow * 128) + (((uint32_t)(ks * 32 + acol)) ^ cxA);
            const uint32_t boff = (uint32_t)(brow * 128) + (((uint32_t)(ks * 32 + bcol)) ^ cxB);

            uint32_t ah[MI][4], al[MI][4], bh[4][2];
#pragma unroll
            for (int mi = 0; mi < MI; mi++) {
                ldsm_x4(ah[mi][0], ah[mi][1], ah[mi][2], ah[mi][3], sAh + aoff + mi * 2048u);
                ldsm_x4(al[mi][0], al[mi][1], al[mi][2], al[mi][3], sAl + aoff + mi * 2048u);
            }
#pragma unroll
            for (int p = 0; p < 2; p++)
                ldsm_x4(bh[2 * p][0], bh[2 * p][1], bh[2 * p + 1][0], bh[2 * p + 1][1],
                        sBh + boff + p * 2048u);
#pragma unroll
            for (int mi = 0; mi < MI; mi++)
#pragma unroll
                for (int nj = 0; nj < 4; nj++) {
                    mma16816(acc[mi][nj], ah[mi], bh[nj]);
                    mma16816(acc[mi][nj], al[mi], bh[nj]);
                }
        }

        __syncthreads();
        if (it + 3 < nIter) {
            load_tile<MI * 32>(sb,          Ahi, bm, lda, (it + 3) * 64, tid);
            load_tile<MI * 32>(sb + SA,     Alo, bm, lda, (it + 3) * 64, tid);
            load_tile<128>    (sb + 2 * SA, Bh,  bn, ldb, (it + 3) * 64, tid);
        }
        CP_COMMIT();
        buf = (buf == 2) ? 0 : buf + 1;
    }

#pragma unroll
    for (int mi = 0; mi < MI; mi++) {
        const int r0 = bm + wm * (MI * 16) + mi * 16 + (lane >> 2);
#pragma unroll
        for (int nj = 0; nj < 4; nj++) {
            const int n = bn + wn * 32 + nj * 8 + 2 * (lane & 3);
            float bz0 = 0.f, bz1 = 0.f;
            if (HAS_BIAS) { bz0 = __ldg(&bias[n]); bz1 = __ldg(&bias[n + 1]); }
            *(float2*)(Of + (size_t)r0 * N + n) =
                make_float2(acc[mi][nj][0] + bz0, acc[mi][nj][1] + bz1);
            *(float2*)(Of + (size_t)(r0 + 8) * N + n) =
                make_float2(acc[mi][nj][2] + bz0, acc[mi][nj][3] + bz1);
        }
    }
}

// ---------------------------------------------------------------------------
// Combine partials -> hidden: relu(Ph[i] + Pt[j] + (valid?Pc:Phc) + b1),
// fp16 hi/lo split.
// ---------------------------------------------------------------------------
__global__ void combine_kernel(const int* __restrict__ ids,
                               const float* __restrict__ b1v) {
    int pair = blockIdx.x;
    int b = pair >> 10, i = (pair >> 5) & 31, j = pair & 31;
    const int* pi = ids + (size_t)(b * Kk + i) * 2;
    const int* pj = ids + (size_t)(b * Kk + j) * 2;
    int lo = min(pi[1], pj[1]);
    int hi = max(pi[0], pj[0]);
    bool valid = hi > lo;
    int ii = min(i, j), jj = max(i, j);
    int tri = 32 * ii - (ii * (ii - 1)) / 2 + (jj - ii);

    const float4* pa = (const float4*)&gPsl[0][b * Kk + i][0];
    const float4* pb = (const float4*)&gPsl[1][b * Kk + j][0];
    const float4* pc = valid ? (const float4*)&gPc[b * NCANP + tri][0]
                             : (const float4*)&gPsl[2][b * Kk + i][0];
    const float4* bb = (const float4*)b1v;

    for (int q = threadIdx.x; q < FINNER / 4; q += blockDim.x) {
        float4 va = pa[q], vb = pb[q], vc = pc[q], v1 = bb[q];
        float4 x = make_float4(fmaxf(va.x + vb.x + vc.x + v1.x, 0.f),
                               fmaxf(va.y + vb.y + vc.y + v1.y, 0.f),
                               fmaxf(va.z + vb.z + vc.z + v1.z, 0.f),
                               fmaxf(va.w + vb.w + vc.w + v1.w, 0.f));
        split_store4h(&gHhi[pair][q * 4], &gHlo[pair][q * 4], x);
    }
}

// ---------------------------------------------------------------------------
// Launch graph
// ---------------------------------------------------------------------------
extern "C" void kernel_launch(void* const* d_in, const int* in_sizes, int n_in,
                              void* d_out, int out_size) {
    const float* csr = (const float*)d_in[0];
    const int*   ids = (const int*)  d_in[1];
    const float* tok = (const float*)d_in[2];
    const float* W1  = (const float*)d_in[4];
    const float* b1  = (const float*)d_in[5];
    const float* W2  = (const float*)d_in[6];
    const float* b2  = (const float*)d_in[7];
    float*       out = (float*)d_out;

    void *csrh, *csrl, *ctxh, *ctxl, *w1h, *psl, *pc, *hh, *hl, *w2h;
    cudaGetSymbolAddress(&csrh, gCsrHi);  cudaGetSymbolAddress(&csrl, gCsrLo);
    cudaGetSymbolAddress(&ctxh, gCtxHi);  cudaGetSymbolAddress(&ctxl, gCtxLo);
    cudaGetSymbolAddress(&w1h,  gW1h);
    cudaGetSymbolAddress(&psl,  gPsl);    cudaGetSymbolAddress(&pc,   gPc);
    cudaGetSymbolAddress(&hh,   gHhi);    cudaGetSymbolAddress(&hl,   gHlo);
    cudaGetSymbolAddress(&w2h,  gW2h);

    constexpr int SMEM_MI4 = 3 * (2 * 16384 + 16384);   // 144 KB
    constexpr int SMEM_MI2 = 3 * (2 * 8192 + 16384);    // 96 KB -> 2 CTAs/SM
    cudaFuncSetAttribute(gemm_mma_kernel<4, false>,
                         cudaFuncAttributeMaxDynamicSharedMemorySize, SMEM_MI4);
    cudaFuncSetAttribute(gemm_mma_kernel<2, true>,
                         cudaFuncAttributeMaxDynamicSharedMemorySize, SMEM_MI2);

    // 1) 4-ary range-max tables (levels 4,16,64,256)
    for (int m = 1; m <= 4; m++)
        build_level4_kernel<<<Bb * Ss, Hh / 4>>>(tok, m);

    // 2) operand prep
    split_csr_kernel<<<Bb * Kk, Hh / 4>>>(csr);
    build_ctx_kernel<<<MCTX, Hh / 4>>>(ids, tok);
    transpose_half_kernel<<<dim3(H3 / 32, FINNER / 32), dim3(32, 8)>>>(
        W1, (__half*)w1h, H3, FINNER);
    transpose_half_kernel<<<dim3(FINNER / 32, Hh / 32), dim3(32, 8)>>>(
        W2, (__half*)w2h, FINNER, Hh);

    // 3) Pslice: csr (128xH) x W1 slice z -> gPsl[z]
    gemm_mma_kernel<4, false><<<dim3(FINNER / 128, 1, 3), 256, SMEM_MI4>>>(
        (const __half*)csrh, (const __half*)csrl, (const __half*)w1h,
        nullptr, (float*)psl,
        FINNER, Hh, Hh, H3, Hh, (long long)(Bb * Kk) * FINNER);

    // 4) ctx GEMM: canonical contexts x W1c -> gPc
    gemm_mma_kernel<4, false><<<dim3(FINNER / 128, MCTX / 128, 1), 256, SMEM_MI4>>>(
        (const __half*)ctxh, (const __half*)ctxl, (const __half*)w1h + 2 * Hh,
        nullptr, (float*)pc,
        FINNER, Hh, Hh, H3, 0, 0);

    // 5) combine partials -> hidden (relu, fp16 split)
    combine_kernel<<<Mrows, 256>>>(ids, b1);

    // 6) GEMM2: hidden x W2 + b2 -> out (64x128 tiles, 2 CTAs/SM)
    gemm_mma_kernel<2, true><<<dim3(Hh / 128, Mrows / 64, 1), 256, SMEM_MI2>>>(
        (const __half*)hh, (const __half*)hl, (const __half*)w2h,
        b2, out,
        Hh, FINNER, FINNER, FINNER, 0, 0);
}

// round 6
// speedup vs baseline: 12.5155x; 1.5824x over previous
#include <cuda_runtime.h>
#include <cuda_fp16.h>
#include <cstdint>
#include <cstddef>

// Problem constants
#define Bb     4
#define Kk     32
#define Ss     512
#define Hh     768
#define H3     2304
#define FINNER 3456
#define Mrows  4096
#define NCAN   528
#define NCANP  544
#define MCTX   2176           // 4 * 544 canonical ctx rows (padded)
#define MCTXT  2304           // MCTX + 128 csr rows appended

// ---------------- device scratch (allocation-free) ----------------
__device__ float  g_tab[4][Bb][Ss][Hh];       // 4-ary range-max tables (25 MB)
__device__ __half gCtxHi[MCTXT][Hh];          // [ctx canonical | csr] fp16
__device__ __half gW1ab[2 * FINNER][Hh];      // W1^T slices a,b  [n][k0..768)
__device__ __half gW1c[FINNER][Hh];           // W1^T slice c
__device__ float  gPc[MCTXT][FINNER];         // [ctx*W1c | head*W1c]
__device__ float  gPsl01[Bb * Kk][2 * FINNER];// head*W1a | tail*W1b (concat on N)
__device__ __half gHh[Mrows][FINNER];         // hidden fp16
__device__ __half gW2h[Hh][FINNER];           // W2^T fp16 [n][k]

// ---------------- helpers ----------------
__device__ __forceinline__ uint32_t smem_to_u32(const void* p) {
    uint32_t a;
    asm("{ .reg .u64 t; cvta.to.shared.u64 t, %1; cvt.u32.u64 %0, t; }" : "=r"(a) : "l"(p));
    return a;
}

#define SMEM_SWIZZLE_128B(o) ((o) ^ (((o) >> 3) & 0x70))

__device__ __forceinline__ void cp16(uint32_t dst, const void* src) {
    asm volatile("cp.async.cg.shared.global [%0], [%1], 16;" :: "r"(dst), "l"(src));
}
#define CP_COMMIT()  asm volatile("cp.async.commit_group;" ::: "memory")
#define CP_WAIT2()   asm volatile("cp.async.wait_group 2;" ::: "memory")

__device__ __forceinline__ void ldsm_x4(uint32_t& r0, uint32_t& r1, uint32_t& r2, uint32_t& r3,
                                        uint32_t addr) {
    asm volatile("ldmatrix.sync.aligned.m8n8.x4.shared.b16 {%0,%1,%2,%3}, [%4];"
                 : "=r"(r0), "=r"(r1), "=r"(r2), "=r"(r3) : "r"(addr));
}

__device__ __forceinline__ void mma16816(float* c, const uint32_t* a, const uint32_t* b) {
    asm volatile(
        "mma.sync.aligned.m16n8k16.row.col.f32.f16.f16.f32 "
        "{%0,%1,%2,%3},{%4,%5,%6,%7},{%8,%9},{%0,%1,%2,%3};"
        : "+f"(c[0]), "+f"(c[1]), "+f"(c[2]), "+f"(c[3])
        : "r"(a[0]), "r"(a[1]), "r"(a[2]), "r"(a[3]), "r"(b[0]), "r"(b[1]));
}

__device__ __forceinline__ float4 fmax4(float4 a, float4 b) {
    return make_float4(fmaxf(a.x, b.x), fmaxf(a.y, b.y), fmaxf(a.z, b.z), fmaxf(a.w, b.w));
}

__device__ __forceinline__ void store4h(__half* p, float4 v) {
    *(ushort4*)p = make_ushort4(__half_as_ushort(__float2half_rn(v.x)),
                                __half_as_ushort(__float2half_rn(v.y)),
                                __half_as_ushort(__float2half_rn(v.z)),
                                __half_as_ushort(__float2half_rn(v.w)));
}

// ---------------------------------------------------------------------------
// Fused 4-ary range-max table build: one block per (8-float chunk, batch);
// computes levels 4,16,64,256 in smem ping-pong, writes each level out.
// fp32 max is assoc/idempotent -> overlapping covers stay bit-exact.
// ---------------------------------------------------------------------------
__global__ void build_tables_kernel(const float* __restrict__ tok) {
    __shared__ float buf[2][Ss][8];
    int hc = blockIdx.x;                 // 0..95
    int b  = blockIdx.y;                 // 0..3
    int tid = threadIdx.x;               // 0..127
    const float* base = tok + (size_t)b * Ss * Hh + hc * 8;

    for (int s = tid; s < Ss; s += 128) {
        *(float4*)&buf[0][s][0] = *(const float4*)(base + (size_t)s * Hh);
        *(float4*)&buf[0][s][4] = *(const float4*)(base + (size_t)s * Hh + 4);
    }
    int cur = 0;
    for (int m = 1; m <= 4; m++) {
        __syncthreads();
        int q = 1 << (2 * (m - 1));
        for (int s = tid; s < Ss; s += 128) {
            int s1 = min(s + q, Ss - 1), s2 = min(s + 2 * q, Ss - 1), s3 = min(s + 3 * q, Ss - 1);
            float4 r0 = fmax4(fmax4(*(float4*)&buf[cur][s][0], *(float4*)&buf[cur][s1][0]),
                              fmax4(*(float4*)&buf[cur][s2][0], *(float4*)&buf[cur][s3][0]));
            float4 r1 = fmax4(fmax4(*(float4*)&buf[cur][s][4], *(float4*)&buf[cur][s1][4]),
                              fmax4(*(float4*)&buf[cur][s2][4], *(float4*)&buf[cur][s3][4]));
            *(float4*)&buf[cur ^ 1][s][0] = r0;
            *(float4*)&buf[cur ^ 1][s][4] = r1;
            float* g = &g_tab[m - 1][b][s][hc * 8];
            *(float4*)g = r0;
            *(float4*)(g + 4) = r1;
        }
        cur ^= 1;
    }
}

// ---------------------------------------------------------------------------
// csr -> fp16, appended at gCtxHi rows 2176..2303
// ---------------------------------------------------------------------------
__global__ void split_csr_kernel(const float* __restrict__ csr) {
    int row = blockIdx.x, t = threadIdx.x;
    float4 v = ((const float4*)(csr + (size_t)row * Hh))[t];
    store4h(&gCtxHi[MCTX + row][t * 4], v);
}

// ---------------------------------------------------------------------------
// Canonical context rows (i<=j): range-max via <=4 overlapping 4^m blocks.
// ---------------------------------------------------------------------------
__global__ void build_ctx_kernel(const int* __restrict__ ids,
                                 const float* __restrict__ tok) {
    int r = blockIdx.x;
    int b = r / NCANP, t = r % NCANP;
    int tt = threadIdx.x;
    float4 cv = make_float4(0.f, 0.f, 0.f, 0.f);

    if (t < NCAN) {
        int i = 0, rem = t;
        while (rem >= 32 - i) { rem -= 32 - i; i++; }
        int j = i + rem;
        const int* pi = ids + (size_t)(b * Kk + i) * 2;
        const int* pj = ids + (size_t)(b * Kk + j) * 2;
        int lo = min(pi[1], pj[1]);
        int hi = max(pi[0], pj[0]);
        if (hi > lo) {
            int len = hi - lo;
            int m  = (31 - __clz(len)) >> 1;      // floor(log4 len)
            int p  = 1 << (2 * m);
            int d  = len - p;
            int s0 = lo;
            int s1 = lo + (d + 2) / 3;
            int s2 = lo + (2 * d + 2) / 3;
            int s3 = hi - p;
            const float *q0, *q1, *q2, *q3;
            if (m == 0) {
                const float* base = tok + (size_t)b * Ss * Hh;
                q0 = base + (size_t)s0 * Hh; q1 = base + (size_t)s1 * Hh;
                q2 = base + (size_t)s2 * Hh; q3 = base + (size_t)s3 * Hh;
            } else {
                q0 = &g_tab[m - 1][b][s0][0]; q1 = &g_tab[m - 1][b][s1][0];
                q2 = &g_tab[m - 1][b][s2][0]; q3 = &g_tab[m - 1][b][s3][0];
            }
            cv = fmax4(fmax4(((const float4*)q0)[tt], ((const float4*)q1)[tt]),
                       fmax4(((const float4*)q2)[tt], ((const float4*)q3)[tt]));
        }
    }
    store4h(&gCtxHi[r][tt * 4], cv);
}

// ---------------------------------------------------------------------------
// W1 transpose (permuted by K-slice): out[n][k] = fp16(W1[k][n]) into
// slice a -> gW1ab[n], slice b -> gW1ab[3456+n], slice c -> gW1c[n].
// ---------------------------------------------------------------------------
__global__ void transpose_w1_kernel(const float* __restrict__ W1) {
    __shared__ float tile[32][33];
    int k0 = blockIdx.x * 32, n0 = blockIdx.y * 32;
    int tx = threadIdx.x, ty = threadIdx.y;
#pragma unroll
    for (int r = ty; r < 32; r += 8)
        tile[r][tx] = W1[(size_t)(k0 + r) * FINNER + n0 + tx];
    __syncthreads();
#pragma unroll
    for (int r = ty; r < 32; r += 8) {
        __half v = __float2half_rn(tile[tx][r]);        // W1[k0+tx][n0+r]
        if (k0 < Hh)            gW1ab[n0 + r][k0 + tx] = v;
        else if (k0 < 2 * Hh)   gW1ab[FINNER + n0 + r][k0 - Hh + tx] = v;
        else                    gW1c[n0 + r][k0 - 2 * Hh + tx] = v;
    }
}

__global__ void transpose_w2_kernel(const float* __restrict__ W2) {
    __shared__ float tile[32][33];
    int k0 = blockIdx.x * 32, n0 = blockIdx.y * 32;
    int tx = threadIdx.x, ty = threadIdx.y;
#pragma unroll
    for (int r = ty; r < 32; r += 8)
        tile[r][tx] = W2[(size_t)(k0 + r) * Hh + n0 + tx];
    __syncthreads();
#pragma unroll
    for (int r = ty; r < 32; r += 8)
        gW2h[n0 + r][k0 + tx] = __float2half_rn(tile[tx][r]);
}

// ---------------------------------------------------------------------------
// Single-product fp16 GEMM core: C = A * B^T (+bias), fp32 out.
// CTA tile (MI*32) x 128, BK=64, 3-stage cp.async, 8 warps.
// lda = ldb = Kd.
// ---------------------------------------------------------------------------
template <int AROWS>
__device__ __forceinline__ void load_tile(uint32_t sbuf, const __half* g,
                                          int row0, int ld, int k0, int tid) {
    const char* gp = (const char*)(g + (size_t)row0 * ld + k0);
    size_t rs = (size_t)ld * 2;
#pragma unroll
    for (int c = 0; c < (AROWS * 8) / 256; c++) {
        int idx = tid + c * 256;
        int row = idx >> 3, seg = idx & 7;
        uint32_t off = (uint32_t)(row * 128 + seg * 16);
        cp16(sbuf + SMEM_SWIZZLE_128B(off), gp + (size_t)row * rs + seg * 16);
    }
}

template <int MI, bool HAS_BIAS>
__device__ __forceinline__ void gemm_body(const __half* __restrict__ A,
                                          const __half* __restrict__ B,
                                          const float* __restrict__ bias,
                                          float* __restrict__ C,
                                          int ldC, int Kd, int bm, int bn) {
    constexpr uint32_t SA    = (uint32_t)MI * 4096u;
    constexpr uint32_t STAGE = SA + 16384u;

    extern __shared__ __align__(1024) char dsm[];
    const uint32_t tiles = smem_to_u32(dsm);

    const int tid = threadIdx.x, wid = tid >> 5, lane = tid & 31;
    const int wm = wid >> 2, wn = wid & 3;

    const int arow = wm * (MI * 16) + (lane & 7) + 8 * ((lane >> 3) & 1);
    const int acol = ((lane >> 4) & 1) * 16;
    const uint32_t cxA = (uint32_t)(arow & 7) << 4;
    const int brow = wn * 32 + (lane & 7) + 8 * ((lane >> 4) & 1);
    const int bcol = ((lane >> 3) & 1) * 16;
    const uint32_t cxB = (uint32_t)(brow & 7) << 4;

    float acc[MI][4][4];
#pragma unroll
    for (int mi = 0; mi < MI; mi++)
#pragma unroll
        for (int nj = 0; nj < 4; nj++)
#pragma unroll
            for (int q = 0; q < 4; q++) acc[mi][nj][q] = 0.0f;

    const int nIter = Kd >> 6;

#pragma unroll
    for (int s = 0; s < 3; s++) {
        uint32_t sb = tiles + s * STAGE;
        load_tile<MI * 32>(sb,      A, bm, Kd, s * 64, tid);
        load_tile<128>    (sb + SA, B, bn, Kd, s * 64, tid);
        CP_COMMIT();
    }

    int buf = 0;
    for (int it = 0; it < nIter; ++it) {
        CP_WAIT2();
        __syncthreads();

        const uint32_t sb  = tiles + (uint32_t)buf * STAGE;
        const uint32_t sAh = sb, sBh = sb + SA;

#pragma unroll
        for (int ks = 0; ks < 4; ks++) {
            const uint32_t aoff = (uint32_t)(arow * 128) + (((uint32_t)(ks * 32 + acol)) ^ cxA);
            const uint32_t boff = (uint32_t)(brow * 128) + (((uint32_t)(ks * 32 + bcol)) ^ cxB);

            uint32_t ah[MI][4], bh[4][2];
#pragma unroll
            for (int mi = 0; mi < MI; mi++)
                ldsm_x4(ah[mi][0], ah[mi][1], ah[mi][2], ah[mi][3], sAh + aoff + mi * 2048u);
#pragma unroll
            for (int p = 0; p < 2; p++)
                ldsm_x4(bh[2 * p][0], bh[2 * p][1], bh[2 * p + 1][0], bh[2 * p + 1][1],
                        sBh + boff + p * 2048u);
#pragma unroll
            for (int mi = 0; mi < MI; mi++)
#pragma unroll
                for (int nj = 0; nj < 4; nj++)
                    mma16816(acc[mi][nj], ah[mi], bh[nj]);
        }

        __syncthreads();
        if (it + 3 < nIter) {
            load_tile<MI * 32>(sb,      A, bm, Kd, (it + 3) * 64, tid);
            load_tile<128>    (sb + SA, B, bn, Kd, (it + 3) * 64, tid);
        }
        CP_COMMIT();
        buf = (buf == 2) ? 0 : buf + 1;
    }

#pragma unroll
    for (int mi = 0; mi < MI; mi++) {
        const int r0 = bm + wm * (MI * 16) + mi * 16 + (lane >> 2);
#pragma unroll
        for (int nj = 0; nj < 4; nj++) {
            const int n = bn + wn * 32 + nj * 8 + 2 * (lane & 3);
            float bz0 = 0.f, bz1 = 0.f;
            if (HAS_BIAS) { bz0 = __ldg(&bias[n]); bz1 = __ldg(&bias[n + 1]); }
            *(float2*)(C + (size_t)r0 * ldC + n) =
                make_float2(acc[mi][nj][0] + bz0, acc[mi][nj][1] + bz1);
            *(float2*)(C + (size_t)(r0 + 8) * ldC + n) =
                make_float2(acc[mi][nj][2] + bz0, acc[mi][nj][3] + bz1);
        }
    }
}

// GEMM1 fused: 540 CTAs. ids < 486: [ctx|csr](2304) x W1c -> gPc (27 x 18).
//              ids >= 486: csr(128) x W1ab (N=6912) -> gPsl01 (54).
__global__ __launch_bounds__(256)
void gemm1_kernel() {
    int id = blockIdx.x;
    if (id < 486) {
        int by = id / 27, bx = id % 27;
        gemm_body<4, false>(&gCtxHi[0][0], &gW1c[0][0], nullptr, &gPc[0][0],
                            FINNER, Hh, by * 128, bx * 128);
    } else {
        int bx = id - 486;
        gemm_body<4, false>(&gCtxHi[MCTX][0], &gW1ab[0][0], nullptr, &gPsl01[0][0],
                            2 * FINNER, Hh, 0, bx * 128);
    }
}

// GEMM2: hidden(4096 x 3456) x W2^T + b2 -> out (64x128 tiles, 2 CTAs/SM)
__global__ __launch_bounds__(256)
void gemm2_kernel(const float* __restrict__ b2, float* __restrict__ out) {
    gemm_body<2, true>(&gHh[0][0], &gW2h[0][0], b2, out,
                       Hh, FINNER, blockIdx.y * 64, blockIdx.x * 128);
}

// ---------------------------------------------------------------------------
// Combine partials -> hidden: relu(Pa[i] + Pb[j] + (valid?Pc:Phc) + b1) -> fp16
// ---------------------------------------------------------------------------
__global__ void combine_kernel(const int* __restrict__ ids,
                               const float* __restrict__ b1v) {
    int pair = blockIdx.x;
    int b = pair >> 10, i = (pair >> 5) & 31, j = pair & 31;
    const int* pi = ids + (size_t)(b * Kk + i) * 2;
    const int* pj = ids + (size_t)(b * Kk + j) * 2;
    int lo = min(pi[1], pj[1]);
    int hi = max(pi[0], pj[0]);
    bool valid = hi > lo;
    int ii = min(i, j), jj = max(i, j);
    int tri = 32 * ii - (ii * (ii - 1)) / 2 + (jj - ii);

    const float4* pa = (const float4*)&gPsl01[b * Kk + i][0];        // head*W1a
    const float4* pb = (const float4*)&gPsl01[b * Kk + j][FINNER];   // tail*W1b
    const float4* pc = valid ? (const float4*)&gPc[b * NCANP + tri][0]
                             : (const float4*)&gPc[MCTX + b * Kk + i][0];
    const float4* bb = (const float4*)b1v;

    for (int q = threadIdx.x; q < FINNER / 4; q += blockDim.x) {
        float4 va = pa[q], vb = pb[q], vc = pc[q], v1 = bb[q];
        float4 x = make_float4(fmaxf(va.x + vb.x + vc.x + v1.x, 0.f),
                               fmaxf(va.y + vb.y + vc.y + v1.y, 0.f),
                               fmaxf(va.z + vb.z + vc.z + v1.z, 0.f),
                               fmaxf(va.w + vb.w + vc.w + v1.w, 0.f));
        store4h(&gHh[pair][q * 4], x);
    }
}

// ---------------------------------------------------------------------------
// Launch graph
// ---------------------------------------------------------------------------
extern "C" void kernel_launch(void* const* d_in, const int* in_sizes, int n_in,
                              void* d_out, int out_size) {
    const float* csr = (const float*)d_in[0];
    const int*   ids = (const int*)  d_in[1];
    const float* tok = (const float*)d_in[2];
    const float* W1  = (const float*)d_in[4];
    const float* b1  = (const float*)d_in[5];
    const float* W2  = (const float*)d_in[6];
    const float* b2  = (const float*)d_in[7];
    float*       out = (float*)d_out;

    constexpr int SMEM_G1 = 3 * (4 * 4096 + 16384);   // 96 KB (MI=4)
    constexpr int SMEM_G2 = 3 * (2 * 4096 + 16384);   // 72 KB (MI=2)
    cudaFuncSetAttribute(gemm1_kernel,
                         cudaFuncAttributeMaxDynamicSharedMemorySize, SMEM_G1);
    cudaFuncSetAttribute(gemm2_kernel,
                         cudaFuncAttributeMaxDynamicSharedMemorySize, SMEM_G2);

    // 1) fused 4-ary range-max tables
    build_tables_kernel<<<dim3(Hh / 8, Bb), 128>>>(tok);

    // 2) operand prep
    split_csr_kernel<<<Bb * Kk, Hh / 4>>>(csr);
    build_ctx_kernel<<<MCTX, Hh / 4>>>(ids, tok);
    transpose_w1_kernel<<<dim3(H3 / 32, FINNER / 32), dim3(32, 8)>>>(W1);
    transpose_w2_kernel<<<dim3(FINNER / 32, Hh / 32), dim3(32, 8)>>>(W2);

    // 3) fused GEMM1 (ctx+head partials and head/tail slices in one grid)
    gemm1_kernel<<<540, 256, SMEM_G1>>>();

    // 4) combine partials -> hidden (relu, fp16)
    combine_kernel<<<Mrows, 256>>>(ids, b1);

    // 5) GEMM2 -> out
    gemm2_kernel<<<dim3(Hh / 128, Mrows / 64), 256, SMEM_G2>>>(b2, out);
}